// round 15
// baseline (speedup 1.0000x reference)
#include <cuda_runtime.h>
#include <cuda_fp16.h>
#include <math.h>
#include <stdint.h>

#define N_ASSET 8192
#define DLAT    512
#define NQKV    1536   // 3 * DLAT

// ---------------------------------------------------------------------------
// Scratch (__device__ globals; allocation-free rule)
// ---------------------------------------------------------------------------
__device__ __half g_zh[(size_t)N_ASSET * DLAT];
__device__ __half g_wh[3][(size_t)DLAT * DLAT];    // contiguous: [1536][512]
__device__ float  g_b3[NQKV];                      // concat bias
__device__ __half g_qkv[(size_t)N_ASSET * NQKV];   // q|k|v, ld=1536
__device__ __half g_vth[(size_t)DLAT * N_ASSET];   // v^T [D][N]
__device__ __half g_sh[(size_t)N_ASSET * N_ASSET]; // fp16 scores
__device__ __half g_ah[(size_t)N_ASSET * N_ASSET]; // fp16 attn

// ---------------------------------------------------------------------------
// Helpers
// ---------------------------------------------------------------------------
__device__ __forceinline__ uint32_t smem_u32(const void* p) {
    uint32_t a;
    asm("{ .reg .u64 t; cvta.to.shared.u64 t, %1; cvt.u32.u64 %0, t; }" : "=r"(a) : "l"(p));
    return a;
}

__device__ __forceinline__ void cp16s(uint32_t sdst, const void* src) {
    asm volatile("cp.async.cg.shared.global [%0], [%1], 16;\n" :: "r"(sdst), "l"(src));
}

#define LDSM_X4(r0, r1, r2, r3, addr) \
    asm volatile("ldmatrix.sync.aligned.m8n8.x4.shared.b16 {%0,%1,%2,%3}, [%4];" \
        : "=r"(r0), "=r"(r1), "=r"(r2), "=r"(r3) : "r"(addr))

#define MMA_F16(d, a0, a1, a2, a3, b0, b1)                                      \
    asm volatile(                                                               \
        "mma.sync.aligned.m16n8k16.row.col.f32.f16.f16.f32 "                    \
        "{%0,%1,%2,%3}, {%4,%5,%6,%7}, {%8,%9}, {%0,%1,%2,%3};\n"               \
        : "+f"(d[0]), "+f"(d[1]), "+f"(d[2]), "+f"(d[3])                        \
        : "r"(a0), "r"(a1), "r"(a2), "r"(a3), "r"(b0), "r"(b1))

// ---------------------------------------------------------------------------
// Fused prep: z -> fp16; Wq|Wk|Wv -> fp16; bias concat
// ---------------------------------------------------------------------------
__global__ __launch_bounds__(256)
void prep_kernel(const float* __restrict__ z,
                 const float* __restrict__ Wq, const float* __restrict__ Wk,
                 const float* __restrict__ Wv,
                 const float* __restrict__ bq, const float* __restrict__ bk,
                 const float* __restrict__ bv,
                 __half* __restrict__ zh, __half* __restrict__ wh,
                 float* __restrict__ b3)
{
    const size_t ZN  = (size_t)N_ASSET * DLAT;
    const size_t WN1 = (size_t)DLAT * DLAT;
    const size_t TOT = ZN + 3 * WN1 + NQKV;
    size_t i = (size_t)blockIdx.x * blockDim.x + threadIdx.x;
    size_t stride = (size_t)gridDim.x * blockDim.x;
    for (; i < TOT; i += stride) {
        if (i < ZN) {
            zh[i] = __float2half(z[i]);
        } else if (i < ZN + 3 * WN1) {
            size_t j = i - ZN;
            float x = (j < WN1) ? Wq[j] : (j < 2 * WN1) ? Wk[j - WN1] : Wv[j - 2 * WN1];
            wh[j] = __float2half(x);
        } else {
            size_t j = i - ZN - 3 * WN1;
            b3[j] = (j < DLAT) ? bq[j] : (j < 2 * (size_t)DLAT) ? bk[j - DLAT]
                                                                : bv[j - 2 * DLAT];
        }
    }
}

// transpose with row stride: x[rows][cols] (ld=ldx) -> y[cols][rows]
__global__ __launch_bounds__(256)
void trans_half_kernel(const __half* __restrict__ x,
                       __half* __restrict__ y, int rows, int cols, int ldx)
{
    __shared__ __half t[32][33];
    const int bx = blockIdx.x * 32;
    const int by = blockIdx.y * 32;
    const int tx = threadIdx.x, ty = threadIdx.y;

    #pragma unroll
    for (int j = 0; j < 4; ++j)
        t[ty + j * 8][tx] = x[(size_t)(by + ty + j * 8) * ldx + bx + tx];
    __syncthreads();

    #pragma unroll
    for (int j = 0; j < 4; ++j)
        y[(size_t)(bx + ty + j * 8) * rows + by + tx] = t[tx][ty + j * 8];
}

// ---------------------------------------------------------------------------
// fp16 NT GEMM, CTA tile 128x128, 8 warps of 64x32, GBK=32, NSTG=4, ldmatrix.
// R10-proven pipeline: wait(3) -> sync -> compute -> sync -> load next.
// Smem row: 64 B data + 16 B pad = 80 B (ldmatrix conflict-free).
// ---------------------------------------------------------------------------
#define GBK 32
#define ROWB 80
#define TILE_B (128 * ROWB)                  // 10240
#define NSTG 4

__global__ __launch_bounds__(256, 2)
void gemm_f16_nt(const __half* __restrict__ Ah,
                 const __half* __restrict__ Bh,
                 const float* __restrict__ bias,
                 float* __restrict__ C,
                 __half* __restrict__ Oh,
                 int M, int N, int K, int lda, int ldb, float scale)
{
    constexpr uint32_t STAGE_B = 2 * TILE_B;

    extern __shared__ __align__(128) char dsm[];
    const uint32_t sb = smem_u32(dsm);

    const int tid = threadIdx.x, lane = tid & 31, wid = tid >> 5;
    const int bm = blockIdx.y * 128, bn = blockIdx.x * 128;
    const int wm = (wid >> 2) * 64, wn = (wid & 3) * 32;
    const int g = lane >> 2, tg = lane & 3;

    float acc[4][4][4];
    #pragma unroll
    for (int i = 0; i < 4; ++i)
        #pragma unroll
        for (int j = 0; j < 4; ++j)
            #pragma unroll
            for (int q = 0; q < 4; ++q) acc[i][j][q] = 0.0f;

    const int KT = K / GBK;

    // loader: thread covers 2 consecutive 16B chunks; 4 chunks per 64B row
    const int lrow = tid >> 1, lc0 = (tid & 1) * 2;
    auto load_stage = [&](int kt, int s) {
        const size_t k0 = (size_t)kt * GBK;
        const uint32_t stb = sb + s * STAGE_B;
        #pragma unroll
        for (int t = 0; t < 2; ++t) {
            const __half* src =
                (t == 0) ? Ah + (size_t)(bm + lrow) * lda
                         : Bh + (size_t)(bn + lrow) * ldb;
            const uint32_t dst = stb + t * TILE_B + (uint32_t)lrow * ROWB + lc0 * 16;
            #pragma unroll
            for (int q = 0; q < 2; ++q)
                cp16s(dst + q * 16, src + k0 + (lc0 + q) * 8);
        }
    };

    // prologue: fill all stages (KT >= NSTG at every call site)
    #pragma unroll
    for (int p = 0; p < NSTG; ++p) {
        load_stage(p, p);
        asm volatile("cp.async.commit_group;\n");
    }

    const uint32_t aRowOff = (uint32_t)(wm + (lane & 15)) * ROWB + (uint32_t)(lane >> 4) * 16;
    const uint32_t bRowOff = (uint32_t)(wn + ((lane >> 4) << 3) + (lane & 7)) * ROWB
                           + (uint32_t)((lane >> 3) & 1) * 16;

    for (int kt = 0; kt < KT; ++kt) {
        const int s = kt % NSTG;

        asm volatile("cp.async.wait_group %0;\n" :: "n"(NSTG - 1));  // chunk kt resident
        __syncthreads();

        const uint32_t stg = sb + s * STAGE_B;
        const uint32_t aHb = stg + aRowOff;
        const uint32_t bHb = stg + TILE_B + bRowOff;

        // hoist B fragments for the BK=32 chunk (both 16-deep halves)
        uint32_t bh[2][4][2];
        #pragma unroll
        for (int h2 = 0; h2 < 2; ++h2) {
            const uint32_t ko = h2 * 32;
            #pragma unroll
            for (int p = 0; p < 2; ++p) {
                LDSM_X4(bh[h2][2 * p][0], bh[h2][2 * p][1],
                        bh[h2][2 * p + 1][0], bh[h2][2 * p + 1][1],
                        bHb + p * (16 * ROWB) + ko);
            }
        }

        // A-fragment register pipeline: 8 steps (2 k-halves x 4 m-tiles)
        uint32_t aCur[4], aNxt[4];
        LDSM_X4(aCur[0], aCur[1], aCur[2], aCur[3], aHb);
        #pragma unroll
        for (int st = 0; st < 8; ++st) {
            const int h2 = st >> 2, mi = st & 3;
            if (st < 7) {
                const int sn = st + 1;
                LDSM_X4(aNxt[0], aNxt[1], aNxt[2], aNxt[3],
                        aHb + (sn & 3) * (16 * ROWB) + (sn >> 2) * 32);
            }
            #pragma unroll
            for (int ni = 0; ni < 4; ++ni) {
                MMA_F16(acc[mi][ni], aCur[0], aCur[1], aCur[2], aCur[3],
                        bh[h2][ni][0], bh[h2][ni][1]);
            }
            #pragma unroll
            for (int r = 0; r < 4; ++r) aCur[r] = aNxt[r];
        }
        __syncthreads();                               // compute done; slot reusable

        if (kt + NSTG < KT) load_stage(kt + NSTG, s);
        asm volatile("cp.async.commit_group;\n");      // always: constant group count
    }

    // epilogue (acc layout: rows g, g+8; cols tg*2, tg*2+1)
    #pragma unroll
    for (int mi = 0; mi < 4; ++mi) {
        const int row0 = bm + wm + mi * 16 + g;
        #pragma unroll
        for (int ni = 0; ni < 4; ++ni) {
            const int col = bn + wn + ni * 8 + tg * 2;
            const float b0 = bias ? bias[col] : 0.0f;
            const float b1 = bias ? bias[col + 1] : 0.0f;
            float r00 = acc[mi][ni][0] * scale + b0;
            float r01 = acc[mi][ni][1] * scale + b1;
            float r10 = acc[mi][ni][2] * scale + b0;
            float r11 = acc[mi][ni][3] * scale + b1;
            if (C) {
                C[(size_t)row0 * N + col]           = r00;
                C[(size_t)row0 * N + col + 1]       = r01;
                C[(size_t)(row0 + 8) * N + col]     = r10;
                C[(size_t)(row0 + 8) * N + col + 1] = r11;
            }
            if (Oh) {
                __half2 hp = {__float2half(r00), __float2half(r01)};
                *(__half2*)&Oh[(size_t)row0 * N + col] = hp;
                __half2 hp2 = {__float2half(r10), __float2half(r11)};
                *(__half2*)&Oh[(size_t)(row0 + 8) * N + col] = hp2;
            }
        }
    }
}

// ---------------------------------------------------------------------------
// Row softmax (N=8192), fp16 in -> fp16 out, __half2 I/O
// ---------------------------------------------------------------------------
__global__ __launch_bounds__(256)
void softmax_half_rows(const __half* __restrict__ Sh, __half* __restrict__ Ah)
{
    const int tid = threadIdx.x;
    const size_t rowoff = (size_t)blockIdx.x * N_ASSET;
    const __half2* s2 = (const __half2*)(Sh + rowoff);
    __half2* a2 = (__half2*)(Ah + rowoff);

    float vx[16], vy[16];
    float m = -3.4e38f;
    #pragma unroll
    for (int j = 0; j < 16; ++j) {
        float2 f = __half22float2(s2[j * 256 + tid]);
        vx[j] = f.x; vy[j] = f.y;
        m = fmaxf(m, fmaxf(f.x, f.y));
    }

    __shared__ float red[8];
    __shared__ float bcast;

    #pragma unroll
    for (int o = 16; o > 0; o >>= 1) m = fmaxf(m, __shfl_xor_sync(0xffffffffu, m, o));
    if ((tid & 31) == 0) red[tid >> 5] = m;
    __syncthreads();
    if (tid < 32) {
        float t = (tid < 8) ? red[tid] : -3.4e38f;
        #pragma unroll
        for (int o = 4; o > 0; o >>= 1) t = fmaxf(t, __shfl_xor_sync(0xffffffffu, t, o));
        if (tid == 0) bcast = t;
    }
    __syncthreads();
    m = bcast;
    __syncthreads();

    float sum = 0.0f;
    #pragma unroll
    for (int j = 0; j < 16; ++j) {
        vx[j] = __expf(vx[j] - m);
        vy[j] = __expf(vy[j] - m);
        sum += vx[j] + vy[j];
    }
    #pragma unroll
    for (int o = 16; o > 0; o >>= 1) sum += __shfl_xor_sync(0xffffffffu, sum, o);
    if ((tid & 31) == 0) red[tid >> 5] = sum;
    __syncthreads();
    if (tid < 32) {
        float t = (tid < 8) ? red[tid] : 0.0f;
        #pragma unroll
        for (int o = 4; o > 0; o >>= 1) t += __shfl_xor_sync(0xffffffffu, t, o);
        if (tid == 0) bcast = t;
    }
    __syncthreads();

    const float inv = 1.0f / bcast;
    #pragma unroll
    for (int j = 0; j < 16; ++j) {
        __half2 o = {__float2half(vx[j] * inv), __float2half(vy[j] * inv)};
        a2[j * 256 + tid] = o;
    }
}

// ---------------------------------------------------------------------------
// kernel_launch
// ---------------------------------------------------------------------------
extern "C" void kernel_launch(void* const* d_in, const int* in_sizes, int n_in,
                              void* d_out, int out_size)
{
    const float* z  = (const float*)d_in[0];
    const float* Wq = (const float*)d_in[1];
    const float* bq = (const float*)d_in[2];
    const float* Wk = (const float*)d_in[3];
    const float* bk = (const float*)d_in[4];
    const float* Wv = (const float*)d_in[5];
    const float* bv = (const float*)d_in[6];
    float* out = (float*)d_out;

    __half *zh, *wh, *qkv, *vth, *sh, *ah;
    float *b3;
    cudaGetSymbolAddress((void**)&zh, g_zh);
    cudaGetSymbolAddress((void**)&wh, g_wh);
    cudaGetSymbolAddress((void**)&b3, g_b3);
    cudaGetSymbolAddress((void**)&qkv, g_qkv);
    cudaGetSymbolAddress((void**)&vth, g_vth);
    cudaGetSymbolAddress((void**)&sh, g_sh);
    cudaGetSymbolAddress((void**)&ah, g_ah);

    const int SMEM = NSTG * 2 * TILE_B;   // 81920 (x2 CTAs = 160 KB/SM)
    cudaFuncSetAttribute((const void*)gemm_f16_nt,
                         cudaFuncAttributeMaxDynamicSharedMemorySize, SMEM);

    dim3 blk(256);

    // 1. fused prep — one launch
    prep_kernel<<<1024, blk>>>(z, Wq, Wk, Wv, bq, bk, bv, zh, wh, b3);

    // 2. merged QKV projection (plain fp16): [8192,1536] = z @ [Wq|Wk|Wv]^T + b3
    dim3 gp(NQKV / 128, N_ASSET / 128);  // 12 x 64 = 768 CTAs
    gemm_f16_nt<<<gp, blk, SMEM>>>(zh, wh, b3,
                                   nullptr, qkv,
                                   N_ASSET, NQKV, DLAT, DLAT, DLAT, 1.0f);

    const __half* qh = qkv;
    const __half* kh = qkv + DLAT;
    const __half* vh = qkv + 2 * DLAT;

    // 3. transpose v -> [D][N]  (v has ld=1536)
    {
        dim3 tb(32, 8);
        dim3 tg(DLAT / 32, N_ASSET / 32);
        trans_half_kernel<<<tg, tb>>>(vh, vth, N_ASSET, DLAT, NQKV);
    }

    // 4. scores = q @ k^T * d^-0.5 -> fp16
    dim3 gs(N_ASSET / 128, N_ASSET / 128);  // 64 x 64
    const float scale = 1.0f / sqrtf((float)DLAT);
    gemm_f16_nt<<<gs, blk, SMEM>>>(qh, kh, nullptr,
                                   nullptr, sh,
                                   N_ASSET, N_ASSET, DLAT, NQKV, NQKV, scale);

    // 5. softmax (fp16 -> fp16)
    softmax_half_rows<<<N_ASSET, blk>>>(sh, ah);

    // 6. h = attn @ v (fp32 out)
    dim3 gh(DLAT / 128, N_ASSET / 128);  // 4 x 64
    gemm_f16_nt<<<gh, blk, SMEM>>>(ah, vth, nullptr,
                                   out, nullptr,
                                   N_ASSET, DLAT, N_ASSET, N_ASSET, N_ASSET, 1.0f);
}

// round 16
// speedup vs baseline: 1.1597x; 1.1597x over previous
#include <cuda_runtime.h>
#include <cuda_fp16.h>
#include <math.h>
#include <stdint.h>

#define N_ASSET 8192
#define DLAT    512
#define NQKV    1536   // 3 * DLAT

// ---------------------------------------------------------------------------
// Scratch (__device__ globals; allocation-free rule)
// ---------------------------------------------------------------------------
__device__ __half g_zh[(size_t)N_ASSET * DLAT];
__device__ __half g_wh[3][(size_t)DLAT * DLAT];    // contiguous: [1536][512]
__device__ float  g_b3[NQKV];                      // concat bias
__device__ __half g_qkv[(size_t)N_ASSET * NQKV];   // q|k|v, ld=1536
__device__ __half g_vth[(size_t)DLAT * N_ASSET];   // v^T [D][N]
__device__ __half g_sh[(size_t)N_ASSET * N_ASSET]; // fp16 scores
__device__ __half g_ah[(size_t)N_ASSET * N_ASSET]; // fp16 attn

// ---------------------------------------------------------------------------
// Helpers
// ---------------------------------------------------------------------------
__device__ __forceinline__ uint32_t smem_u32(const void* p) {
    uint32_t a;
    asm("{ .reg .u64 t; cvta.to.shared.u64 t, %1; cvt.u32.u64 %0, t; }" : "=r"(a) : "l"(p));
    return a;
}

__device__ __forceinline__ void cp16s(uint32_t sdst, const void* src) {
    asm volatile("cp.async.cg.shared.global [%0], [%1], 16;\n" :: "r"(sdst), "l"(src));
}

#define LDSM_X4(r0, r1, r2, r3, addr) \
    asm volatile("ldmatrix.sync.aligned.m8n8.x4.shared.b16 {%0,%1,%2,%3}, [%4];" \
        : "=r"(r0), "=r"(r1), "=r"(r2), "=r"(r3) : "r"(addr))

#define MMA_F16(d, a0, a1, a2, a3, b0, b1)                                      \
    asm volatile(                                                               \
        "mma.sync.aligned.m16n8k16.row.col.f32.f16.f16.f32 "                    \
        "{%0,%1,%2,%3}, {%4,%5,%6,%7}, {%8,%9}, {%0,%1,%2,%3};\n"               \
        : "+f"(d[0]), "+f"(d[1]), "+f"(d[2]), "+f"(d[3])                        \
        : "r"(a0), "r"(a1), "r"(a2), "r"(a3), "r"(b0), "r"(b1))

// ---------------------------------------------------------------------------
// Fused prep: z -> fp16; Wq|Wk|Wv -> fp16; bias concat
// ---------------------------------------------------------------------------
__global__ __launch_bounds__(256)
void prep_kernel(const float* __restrict__ z,
                 const float* __restrict__ Wq, const float* __restrict__ Wk,
                 const float* __restrict__ Wv,
                 const float* __restrict__ bq, const float* __restrict__ bk,
                 const float* __restrict__ bv,
                 __half* __restrict__ zh, __half* __restrict__ wh,
                 float* __restrict__ b3)
{
    const size_t ZN  = (size_t)N_ASSET * DLAT;
    const size_t WN1 = (size_t)DLAT * DLAT;
    const size_t TOT = ZN + 3 * WN1 + NQKV;
    size_t i = (size_t)blockIdx.x * blockDim.x + threadIdx.x;
    size_t stride = (size_t)gridDim.x * blockDim.x;
    for (; i < TOT; i += stride) {
        if (i < ZN) {
            zh[i] = __float2half(z[i]);
        } else if (i < ZN + 3 * WN1) {
            size_t j = i - ZN;
            float x = (j < WN1) ? Wq[j] : (j < 2 * WN1) ? Wk[j - WN1] : Wv[j - 2 * WN1];
            wh[j] = __float2half(x);
        } else {
            size_t j = i - ZN - 3 * WN1;
            b3[j] = (j < DLAT) ? bq[j] : (j < 2 * (size_t)DLAT) ? bk[j - DLAT]
                                                                : bv[j - 2 * DLAT];
        }
    }
}

// transpose with row stride: x[rows][cols] (ld=ldx) -> y[cols][rows]
__global__ __launch_bounds__(256)
void trans_half_kernel(const __half* __restrict__ x,
                       __half* __restrict__ y, int rows, int cols, int ldx)
{
    __shared__ __half t[32][33];
    const int bx = blockIdx.x * 32;
    const int by = blockIdx.y * 32;
    const int tx = threadIdx.x, ty = threadIdx.y;

    #pragma unroll
    for (int j = 0; j < 4; ++j)
        t[ty + j * 8][tx] = x[(size_t)(by + ty + j * 8) * ldx + bx + tx];
    __syncthreads();

    #pragma unroll
    for (int j = 0; j < 4; ++j)
        y[(size_t)(bx + ty + j * 8) * rows + by + tx] = t[tx][ty + j * 8];
}

// ---------------------------------------------------------------------------
// fp16 NT GEMM — byte-level R10 configuration (653.4 µs artifact):
// CTA tile 128x128, 8 warps of 64x32, GBK=32, ROWB=80, ldmatrix,
// loader: lr = tid>>2 (4 threads/row), lh = tid&3 (16 B per thread per pass),
// pipeline: wait(NSTGT-1) -> sync -> compute -> sync -> load next.
// ---------------------------------------------------------------------------
#define GBK 32
#define ROWB 80
#define TILE_B (128 * ROWB)                  // 10240

template<int NSTGT>
__global__ __launch_bounds__(256, 2)
void gemm_f16_nt(const __half* __restrict__ Ah,
                 const __half* __restrict__ Bh,
                 const float* __restrict__ bias,
                 float* __restrict__ C,
                 __half* __restrict__ Oh,
                 int M, int N, int K, int lda, int ldb, float scale)
{
    constexpr int NT = 2;
    constexpr uint32_t STAGE_B = NT * TILE_B;

    extern __shared__ __align__(128) char dsm[];
    const uint32_t sb = smem_u32(dsm);

    const int tid = threadIdx.x, lane = tid & 31, wid = tid >> 5;
    const int bm = blockIdx.y * 128, bn = blockIdx.x * 128;
    const int wm = (wid >> 2) * 64, wn = (wid & 3) * 32;
    const int g = lane >> 2, tg = lane & 3;

    float acc[4][4][4];
    #pragma unroll
    for (int i = 0; i < 4; ++i)
        #pragma unroll
        for (int j = 0; j < 4; ++j)
            #pragma unroll
            for (int q = 0; q < 4; ++q) acc[i][j][q] = 0.0f;

    const int KT = K / GBK;

    // R10 loader mapping: lr = tid>>2 (row 0..63, +64 on second pass), lh = tid&3
    const int lr = tid >> 2, lh = tid & 3;
    auto load_stage = [&](int kt, int s) {
        const size_t k0 = (size_t)kt * GBK;
        const uint32_t stb = sb + s * STAGE_B;
        #pragma unroll
        for (int j = 0; j < 2 * NT; ++j) {
            const int tile = j >> 1;
            const int r = ((j & 1) << 6) + lr;       // 0..127
            const __half* src =
                (tile == 0) ? Ah + (size_t)(bm + r) * lda
                            : Bh + (size_t)(bn + r) * ldb;
            cp16s(stb + tile * TILE_B + r * ROWB + lh * 16, src + k0 + lh * 8);
        }
    };

    // prologue: fill all stages (KT >= NSTGT at every call site)
    #pragma unroll
    for (int p = 0; p < NSTGT; ++p) {
        load_stage(p, p);
        asm volatile("cp.async.commit_group;\n");
    }

    const uint32_t aRowOff = (uint32_t)(wm + (lane & 15)) * ROWB + (uint32_t)(lane >> 4) * 16;
    const uint32_t bRowOff = (uint32_t)(wn + ((lane >> 4) << 3) + (lane & 7)) * ROWB
                           + (uint32_t)((lane >> 3) & 1) * 16;

    for (int kt = 0; kt < KT; ++kt) {
        const int s = kt % NSTGT;

        asm volatile("cp.async.wait_group %0;\n" :: "n"(NSTGT - 1));  // chunk kt resident
        __syncthreads();

        const uint32_t stg = sb + s * STAGE_B;
        const uint32_t aHb = stg + aRowOff;
        const uint32_t bHb = stg + TILE_B + bRowOff;

        // hoist B fragments for the BK=32 chunk (both 16-deep halves)
        uint32_t bh[2][4][2];
        #pragma unroll
        for (int h2 = 0; h2 < 2; ++h2) {
            const uint32_t ko = h2 * 32;
            #pragma unroll
            for (int p = 0; p < 2; ++p) {
                LDSM_X4(bh[h2][2 * p][0], bh[h2][2 * p][1],
                        bh[h2][2 * p + 1][0], bh[h2][2 * p + 1][1],
                        bHb + p * (16 * ROWB) + ko);
            }
        }

        // A-fragment register pipeline: 8 steps (2 k-halves x 4 m-tiles)
        uint32_t aCur[4], aNxt[4];
        LDSM_X4(aCur[0], aCur[1], aCur[2], aCur[3], aHb);
        #pragma unroll
        for (int st = 0; st < 8; ++st) {
            const int h2 = st >> 2, mi = st & 3;
            if (st < 7) {
                const int sn = st + 1;
                LDSM_X4(aNxt[0], aNxt[1], aNxt[2], aNxt[3],
                        aHb + (sn & 3) * (16 * ROWB) + (sn >> 2) * 32);
            }
            #pragma unroll
            for (int ni = 0; ni < 4; ++ni) {
                MMA_F16(acc[mi][ni], aCur[0], aCur[1], aCur[2], aCur[3],
                        bh[h2][ni][0], bh[h2][ni][1]);
            }
            #pragma unroll
            for (int r = 0; r < 4; ++r) aCur[r] = aNxt[r];
        }
        __syncthreads();                               // compute done; slot reusable

        if (kt + NSTGT < KT) load_stage(kt + NSTGT, s);
        asm volatile("cp.async.commit_group;\n");      // always: constant group count
    }

    // epilogue (acc layout: rows g, g+8; cols tg*2, tg*2+1)
    #pragma unroll
    for (int mi = 0; mi < 4; ++mi) {
        const int row0 = bm + wm + mi * 16 + g;
        #pragma unroll
        for (int ni = 0; ni < 4; ++ni) {
            const int col = bn + wn + ni * 8 + tg * 2;
            const float b0 = bias ? bias[col] : 0.0f;
            const float b1 = bias ? bias[col + 1] : 0.0f;
            float r00 = acc[mi][ni][0] * scale + b0;
            float r01 = acc[mi][ni][1] * scale + b1;
            float r10 = acc[mi][ni][2] * scale + b0;
            float r11 = acc[mi][ni][3] * scale + b1;
            if (C) {
                C[(size_t)row0 * N + col]           = r00;
                C[(size_t)row0 * N + col + 1]       = r01;
                C[(size_t)(row0 + 8) * N + col]     = r10;
                C[(size_t)(row0 + 8) * N + col + 1] = r11;
            }
            if (Oh) {
                __half2 hp = {__float2half(r00), __float2half(r01)};
                *(__half2*)&Oh[(size_t)row0 * N + col] = hp;
                __half2 hp2 = {__float2half(r10), __float2half(r11)};
                *(__half2*)&Oh[(size_t)(row0 + 8) * N + col] = hp2;
            }
        }
    }
}

// ---------------------------------------------------------------------------
// Row softmax (N=8192), fp16 in -> fp16 out, __half2 I/O
// ---------------------------------------------------------------------------
__global__ __launch_bounds__(256)
void softmax_half_rows(const __half* __restrict__ Sh, __half* __restrict__ Ah)
{
    const int tid = threadIdx.x;
    const size_t rowoff = (size_t)blockIdx.x * N_ASSET;
    const __half2* s2 = (const __half2*)(Sh + rowoff);
    __half2* a2 = (__half2*)(Ah + rowoff);

    float vx[16], vy[16];
    float m = -3.4e38f;
    #pragma unroll
    for (int j = 0; j < 16; ++j) {
        float2 f = __half22float2(s2[j * 256 + tid]);
        vx[j] = f.x; vy[j] = f.y;
        m = fmaxf(m, fmaxf(f.x, f.y));
    }

    __shared__ float red[8];
    __shared__ float bcast;

    #pragma unroll
    for (int o = 16; o > 0; o >>= 1) m = fmaxf(m, __shfl_xor_sync(0xffffffffu, m, o));
    if ((tid & 31) == 0) red[tid >> 5] = m;
    __syncthreads();
    if (tid < 32) {
        float t = (tid < 8) ? red[tid] : -3.4e38f;
        #pragma unroll
        for (int o = 4; o > 0; o >>= 1) t = fmaxf(t, __shfl_xor_sync(0xffffffffu, t, o));
        if (tid == 0) bcast = t;
    }
    __syncthreads();
    m = bcast;
    __syncthreads();

    float sum = 0.0f;
    #pragma unroll
    for (int j = 0; j < 16; ++j) {
        vx[j] = __expf(vx[j] - m);
        vy[j] = __expf(vy[j] - m);
        sum += vx[j] + vy[j];
    }
    #pragma unroll
    for (int o = 16; o > 0; o >>= 1) sum += __shfl_xor_sync(0xffffffffu, sum, o);
    if ((tid & 31) == 0) red[tid >> 5] = sum;
    __syncthreads();
    if (tid < 32) {
        float t = (tid < 8) ? red[tid] : 0.0f;
        #pragma unroll
        for (int o = 4; o > 0; o >>= 1) t += __shfl_xor_sync(0xffffffffu, t, o);
        if (tid == 0) bcast = t;
    }
    __syncthreads();

    const float inv = 1.0f / bcast;
    #pragma unroll
    for (int j = 0; j < 16; ++j) {
        __half2 o = {__float2half(vx[j] * inv), __float2half(vy[j] * inv)};
        a2[j * 256 + tid] = o;
    }
}

// ---------------------------------------------------------------------------
// kernel_launch
// ---------------------------------------------------------------------------
extern "C" void kernel_launch(void* const* d_in, const int* in_sizes, int n_in,
                              void* d_out, int out_size)
{
    const float* z  = (const float*)d_in[0];
    const float* Wq = (const float*)d_in[1];
    const float* bq = (const float*)d_in[2];
    const float* Wk = (const float*)d_in[3];
    const float* bk = (const float*)d_in[4];
    const float* Wv = (const float*)d_in[5];
    const float* bv = (const float*)d_in[6];
    float* out = (float*)d_out;

    __half *zh, *wh, *qkv, *vth, *sh, *ah;
    float *b3;
    cudaGetSymbolAddress((void**)&zh, g_zh);
    cudaGetSymbolAddress((void**)&wh, g_wh);
    cudaGetSymbolAddress((void**)&b3, g_b3);
    cudaGetSymbolAddress((void**)&qkv, g_qkv);
    cudaGetSymbolAddress((void**)&vth, g_vth);
    cudaGetSymbolAddress((void**)&sh, g_sh);
    cudaGetSymbolAddress((void**)&ah, g_ah);

    const int SMEM = 4 * 2 * TILE_B;   // 81920 (x2 CTAs = 160 KB/SM)
    cudaFuncSetAttribute((const void*)gemm_f16_nt<4>,
                         cudaFuncAttributeMaxDynamicSharedMemorySize, SMEM);

    dim3 blk(256);

    // 1. fused prep — one launch
    prep_kernel<<<1024, blk>>>(z, Wq, Wk, Wv, bq, bk, bv, zh, wh, b3);

    // 2. merged QKV projection (plain fp16): [8192,1536] = z @ [Wq|Wk|Wv]^T + b3
    dim3 gp(NQKV / 128, N_ASSET / 128);  // 12 x 64 = 768 CTAs
    gemm_f16_nt<4><<<gp, blk, SMEM>>>(zh, wh, b3,
                                      nullptr, qkv,
                                      N_ASSET, NQKV, DLAT, DLAT, DLAT, 1.0f);

    const __half* qh = qkv;
    const __half* kh = qkv + DLAT;
    const __half* vh = qkv + 2 * DLAT;

    // 3. transpose v -> [D][N]  (v has ld=1536)
    {
        dim3 tb(32, 8);
        dim3 tg(DLAT / 32, N_ASSET / 32);
        trans_half_kernel<<<tg, tb>>>(vh, vth, N_ASSET, DLAT, NQKV);
    }

    // 4. scores = q @ k^T * d^-0.5 -> fp16
    dim3 gs(N_ASSET / 128, N_ASSET / 128);  // 64 x 64
    const float scale = 1.0f / sqrtf((float)DLAT);
    gemm_f16_nt<4><<<gs, blk, SMEM>>>(qh, kh, nullptr,
                                      nullptr, sh,
                                      N_ASSET, N_ASSET, DLAT, NQKV, NQKV, scale);

    // 5. softmax (fp16 -> fp16)
    softmax_half_rows<<<N_ASSET, blk>>>(sh, ah);

    // 6. h = attn @ v (fp32 out)
    dim3 gh(DLAT / 128, N_ASSET / 128);  // 4 x 64
    gemm_f16_nt<4><<<gh, blk, SMEM>>>(ah, vth, nullptr,
                                      out, nullptr,
                                      N_ASSET, DLAT, N_ASSET, N_ASSET, N_ASSET, 1.0f);
}

// round 17
// speedup vs baseline: 1.2212x; 1.0530x over previous
#include <cuda_runtime.h>
#include <cuda_fp16.h>
#include <math.h>
#include <stdint.h>

#define N_ASSET 8192
#define DLAT    512
#define NQKV    1536   // 3 * DLAT

// ---------------------------------------------------------------------------
// Scratch (__device__ globals; allocation-free rule)
// ---------------------------------------------------------------------------
__device__ __half g_zh[(size_t)N_ASSET * DLAT];
__device__ __half g_wh[3][(size_t)DLAT * DLAT];    // contiguous: [1536][512]
__device__ float  g_b3[NQKV];                      // concat bias
__device__ __half g_qkv[(size_t)N_ASSET * NQKV];   // q|k|v, ld=1536
__device__ __half g_vth[(size_t)DLAT * N_ASSET];   // v^T [D][N]
__device__ __half g_p[(size_t)N_ASSET * N_ASSET];  // fp16 exp(scores) (unnormalized)
__device__ float  g_part[64 * (size_t)N_ASSET];    // per-colblock row sums [cb][row]
__device__ float  g_zinv[N_ASSET];                 // 1 / rowsum

// ---------------------------------------------------------------------------
// Helpers
// ---------------------------------------------------------------------------
__device__ __forceinline__ uint32_t smem_u32(const void* p) {
    uint32_t a;
    asm("{ .reg .u64 t; cvta.to.shared.u64 t, %1; cvt.u32.u64 %0, t; }" : "=r"(a) : "l"(p));
    return a;
}

__device__ __forceinline__ void cp16s(uint32_t sdst, const void* src) {
    asm volatile("cp.async.cg.shared.global [%0], [%1], 16;\n" :: "r"(sdst), "l"(src));
}

#define LDSM_X4(r0, r1, r2, r3, addr) \
    asm volatile("ldmatrix.sync.aligned.m8n8.x4.shared.b16 {%0,%1,%2,%3}, [%4];" \
        : "=r"(r0), "=r"(r1), "=r"(r2), "=r"(r3) : "r"(addr))

#define MMA_F16(d, a0, a1, a2, a3, b0, b1)                                      \
    asm volatile(                                                               \
        "mma.sync.aligned.m16n8k16.row.col.f32.f16.f16.f32 "                    \
        "{%0,%1,%2,%3}, {%4,%5,%6,%7}, {%8,%9}, {%0,%1,%2,%3};\n"               \
        : "+f"(d[0]), "+f"(d[1]), "+f"(d[2]), "+f"(d[3])                        \
        : "r"(a0), "r"(a1), "r"(a2), "r"(a3), "r"(b0), "r"(b1))

// ---------------------------------------------------------------------------
// Fused prep: z -> fp16; Wq|Wk|Wv -> fp16; bias concat
// ---------------------------------------------------------------------------
__global__ __launch_bounds__(256)
void prep_kernel(const float* __restrict__ z,
                 const float* __restrict__ Wq, const float* __restrict__ Wk,
                 const float* __restrict__ Wv,
                 const float* __restrict__ bq, const float* __restrict__ bk,
                 const float* __restrict__ bv,
                 __half* __restrict__ zh, __half* __restrict__ wh,
                 float* __restrict__ b3)
{
    const size_t ZN  = (size_t)N_ASSET * DLAT;
    const size_t WN1 = (size_t)DLAT * DLAT;
    const size_t TOT = ZN + 3 * WN1 + NQKV;
    size_t i = (size_t)blockIdx.x * blockDim.x + threadIdx.x;
    size_t stride = (size_t)gridDim.x * blockDim.x;
    for (; i < TOT; i += stride) {
        if (i < ZN) {
            zh[i] = __float2half(z[i]);
        } else if (i < ZN + 3 * WN1) {
            size_t j = i - ZN;
            float x = (j < WN1) ? Wq[j] : (j < 2 * WN1) ? Wk[j - WN1] : Wv[j - 2 * WN1];
            wh[j] = __float2half(x);
        } else {
            size_t j = i - ZN - 3 * WN1;
            b3[j] = (j < DLAT) ? bq[j] : (j < 2 * (size_t)DLAT) ? bk[j - DLAT]
                                                                : bv[j - 2 * DLAT];
        }
    }
}

// transpose with row stride: x[rows][cols] (ld=ldx) -> y[cols][rows]
__global__ __launch_bounds__(256)
void trans_half_kernel(const __half* __restrict__ x,
                       __half* __restrict__ y, int rows, int cols, int ldx)
{
    __shared__ __half t[32][33];
    const int bx = blockIdx.x * 32;
    const int by = blockIdx.y * 32;
    const int tx = threadIdx.x, ty = threadIdx.y;

    #pragma unroll
    for (int j = 0; j < 4; ++j)
        t[ty + j * 8][tx] = x[(size_t)(by + ty + j * 8) * ldx + bx + tx];
    __syncthreads();

    #pragma unroll
    for (int j = 0; j < 4; ++j)
        y[(size_t)(bx + ty + j * 8) * rows + by + tx] = t[tx][ty + j * 8];
}

// ---------------------------------------------------------------------------
// Row-sum reduce: zinv[row] = 1 / sum_cb part[cb][row]
// ---------------------------------------------------------------------------
__global__ __launch_bounds__(256)
void zinv_kernel(const float* __restrict__ part, float* __restrict__ zinv)
{
    const int row = blockIdx.x * 256 + threadIdx.x;
    float s = 0.0f;
    #pragma unroll
    for (int cb = 0; cb < 64; ++cb)
        s += part[(size_t)cb * N_ASSET + row];
    zinv[row] = 1.0f / s;
}

// ---------------------------------------------------------------------------
// fp16 NT GEMM — R10 engine (proven loader: lr=tid>>2, lh=tid&3), GBK=32,
// ROWB=80, NSTG=4, CTA 128x128, 8 warps of 64x32, ldmatrix + A-reg pipeline.
// EXPOUT=1: write Oh = fp16(__expf(acc*scale)), emit per-row partial sums.
// EXPOUT=0: C = acc*scale + bias (then *zinv[row] if given), or Oh = fp16.
// ---------------------------------------------------------------------------
#define GBK 32
#define ROWB 80
#define TILE_B (128 * ROWB)                  // 10240
#define NSTG 4

template<bool EXPOUT>
__global__ __launch_bounds__(256, 2)
void gemm_f16_nt(const __half* __restrict__ Ah,
                 const __half* __restrict__ Bh,
                 const float* __restrict__ bias,
                 float* __restrict__ C,
                 __half* __restrict__ Oh,
                 float* __restrict__ partSums,        // EXPOUT only
                 const float* __restrict__ zinv,      // fp32-out only
                 int M, int N, int K, int lda, int ldb, float scale)
{
    constexpr int NT = 2;
    constexpr uint32_t STAGE_B = NT * TILE_B;

    extern __shared__ __align__(128) char dsm[];
    const uint32_t sb = smem_u32(dsm);

    const int tid = threadIdx.x, lane = tid & 31, wid = tid >> 5;
    const int bm = blockIdx.y * 128, bn = blockIdx.x * 128;
    const int wm = (wid >> 2) * 64, wn = (wid & 3) * 32;
    const int g = lane >> 2, tg = lane & 3;

    float acc[4][4][4];
    #pragma unroll
    for (int i = 0; i < 4; ++i)
        #pragma unroll
        for (int j = 0; j < 4; ++j)
            #pragma unroll
            for (int q = 0; q < 4; ++q) acc[i][j][q] = 0.0f;

    const int KT = K / GBK;

    // R10 loader: lr = tid>>2 (row 0..63, +64 second pass), lh = tid&3 (16B)
    const int lr = tid >> 2, lh = tid & 3;
    auto load_stage = [&](int kt, int s) {
        const size_t k0 = (size_t)kt * GBK;
        const uint32_t stb = sb + s * STAGE_B;
        #pragma unroll
        for (int j = 0; j < 2 * NT; ++j) {
            const int tile = j >> 1;
            const int r = ((j & 1) << 6) + lr;       // 0..127
            const __half* src =
                (tile == 0) ? Ah + (size_t)(bm + r) * lda
                            : Bh + (size_t)(bn + r) * ldb;
            cp16s(stb + tile * TILE_B + r * ROWB + lh * 16, src + k0 + lh * 8);
        }
    };

    #pragma unroll
    for (int p = 0; p < NSTG; ++p) {
        load_stage(p, p);
        asm volatile("cp.async.commit_group;\n");
    }

    const uint32_t aRowOff = (uint32_t)(wm + (lane & 15)) * ROWB + (uint32_t)(lane >> 4) * 16;
    const uint32_t bRowOff = (uint32_t)(wn + ((lane >> 4) << 3) + (lane & 7)) * ROWB
                           + (uint32_t)((lane >> 3) & 1) * 16;

    for (int kt = 0; kt < KT; ++kt) {
        const int s = kt % NSTG;

        asm volatile("cp.async.wait_group %0;\n" :: "n"(NSTG - 1));
        __syncthreads();

        const uint32_t stg = sb + s * STAGE_B;
        const uint32_t aHb = stg + aRowOff;
        const uint32_t bHb = stg + TILE_B + bRowOff;

        uint32_t bh[2][4][2];
        #pragma unroll
        for (int h2 = 0; h2 < 2; ++h2) {
            const uint32_t ko = h2 * 32;
            #pragma unroll
            for (int p = 0; p < 2; ++p) {
                LDSM_X4(bh[h2][2 * p][0], bh[h2][2 * p][1],
                        bh[h2][2 * p + 1][0], bh[h2][2 * p + 1][1],
                        bHb + p * (16 * ROWB) + ko);
            }
        }

        uint32_t aCur[4], aNxt[4];
        LDSM_X4(aCur[0], aCur[1], aCur[2], aCur[3], aHb);
        #pragma unroll
        for (int st = 0; st < 8; ++st) {
            const int h2 = st >> 2, mi = st & 3;
            if (st < 7) {
                const int sn = st + 1;
                LDSM_X4(aNxt[0], aNxt[1], aNxt[2], aNxt[3],
                        aHb + (sn & 3) * (16 * ROWB) + (sn >> 2) * 32);
            }
            #pragma unroll
            for (int ni = 0; ni < 4; ++ni) {
                MMA_F16(acc[mi][ni], aCur[0], aCur[1], aCur[2], aCur[3],
                        bh[h2][ni][0], bh[h2][ni][1]);
            }
            #pragma unroll
            for (int r = 0; r < 4; ++r) aCur[r] = aNxt[r];
        }
        __syncthreads();

        if (kt + NSTG < KT) load_stage(kt + NSTG, s);
        asm volatile("cp.async.commit_group;\n");
    }

    if constexpr (EXPOUT) {
        // epilogue: p = exp(acc * scale), fp16 out + per-row partial sums
        float rs[4][2];   // [mi][row g / row g+8]
        #pragma unroll
        for (int mi = 0; mi < 4; ++mi) { rs[mi][0] = 0.0f; rs[mi][1] = 0.0f; }

        #pragma unroll
        for (int mi = 0; mi < 4; ++mi) {
            const int row0 = bm + wm + mi * 16 + g;
            #pragma unroll
            for (int ni = 0; ni < 4; ++ni) {
                const int col = bn + wn + ni * 8 + tg * 2;
                float p00 = __expf(acc[mi][ni][0] * scale);
                float p01 = __expf(acc[mi][ni][1] * scale);
                float p10 = __expf(acc[mi][ni][2] * scale);
                float p11 = __expf(acc[mi][ni][3] * scale);
                rs[mi][0] += p00 + p01;
                rs[mi][1] += p10 + p11;
                __half2 hp = {__float2half(p00), __float2half(p01)};
                *(__half2*)&Oh[(size_t)row0 * N + col] = hp;
                __half2 hp2 = {__float2half(p10), __float2half(p11)};
                *(__half2*)&Oh[(size_t)(row0 + 8) * N + col] = hp2;
            }
        }

        // reduce over tg lanes (lane = g*4 + tg)
        #pragma unroll
        for (int mi = 0; mi < 4; ++mi) {
            #pragma unroll
            for (int h = 0; h < 2; ++h) {
                rs[mi][h] += __shfl_xor_sync(0xffffffffu, rs[mi][h], 1);
                rs[mi][h] += __shfl_xor_sync(0xffffffffu, rs[mi][h], 2);
            }
        }
        // smem cross-warp reduce: sred[wn][128 rows]
        float* sred = (float*)dsm;
        if (tg == 0) {
            const int wnid = wid & 3;
            #pragma unroll
            for (int mi = 0; mi < 4; ++mi) {
                sred[wnid * 128 + wm + mi * 16 + g]     = rs[mi][0];
                sred[wnid * 128 + wm + mi * 16 + g + 8] = rs[mi][1];
            }
        }
        __syncthreads();
        if (tid < 128) {
            float s = sred[tid] + sred[128 + tid] + sred[256 + tid] + sred[384 + tid];
            partSums[(size_t)blockIdx.x * M + bm + tid] = s;
        }
    } else {
        #pragma unroll
        for (int mi = 0; mi < 4; ++mi) {
            const int row0 = bm + wm + mi * 16 + g;
            const float zi0 = zinv ? zinv[row0] : 1.0f;
            const float zi1 = zinv ? zinv[row0 + 8] : 1.0f;
            #pragma unroll
            for (int ni = 0; ni < 4; ++ni) {
                const int col = bn + wn + ni * 8 + tg * 2;
                const float b0 = bias ? bias[col] : 0.0f;
                const float b1 = bias ? bias[col + 1] : 0.0f;
                float r00 = acc[mi][ni][0] * scale + b0;
                float r01 = acc[mi][ni][1] * scale + b1;
                float r10 = acc[mi][ni][2] * scale + b0;
                float r11 = acc[mi][ni][3] * scale + b1;
                if (C) {
                    C[(size_t)row0 * N + col]           = r00 * zi0;
                    C[(size_t)row0 * N + col + 1]       = r01 * zi0;
                    C[(size_t)(row0 + 8) * N + col]     = r10 * zi1;
                    C[(size_t)(row0 + 8) * N + col + 1] = r11 * zi1;
                }
                if (Oh) {
                    __half2 hp = {__float2half(r00), __float2half(r01)};
                    *(__half2*)&Oh[(size_t)row0 * N + col] = hp;
                    __half2 hp2 = {__float2half(r10), __float2half(r11)};
                    *(__half2*)&Oh[(size_t)(row0 + 8) * N + col] = hp2;
                }
            }
        }
    }
}

// ---------------------------------------------------------------------------
// kernel_launch
// ---------------------------------------------------------------------------
extern "C" void kernel_launch(void* const* d_in, const int* in_sizes, int n_in,
                              void* d_out, int out_size)
{
    const float* z  = (const float*)d_in[0];
    const float* Wq = (const float*)d_in[1];
    const float* bq = (const float*)d_in[2];
    const float* Wk = (const float*)d_in[3];
    const float* bk = (const float*)d_in[4];
    const float* Wv = (const float*)d_in[5];
    const float* bv = (const float*)d_in[6];
    float* out = (float*)d_out;

    __half *zh, *wh, *qkv, *vth, *p;
    float *b3, *part, *zinv;
    cudaGetSymbolAddress((void**)&zh, g_zh);
    cudaGetSymbolAddress((void**)&wh, g_wh);
    cudaGetSymbolAddress((void**)&b3, g_b3);
    cudaGetSymbolAddress((void**)&qkv, g_qkv);
    cudaGetSymbolAddress((void**)&vth, g_vth);
    cudaGetSymbolAddress((void**)&p, g_p);
    cudaGetSymbolAddress((void**)&part, g_part);
    cudaGetSymbolAddress((void**)&zinv, g_zinv);

    const int SMEM = NSTG * 2 * TILE_B;   // 81920 (x2 CTAs = 160 KB/SM)
    cudaFuncSetAttribute((const void*)gemm_f16_nt<false>,
                         cudaFuncAttributeMaxDynamicSharedMemorySize, SMEM);
    cudaFuncSetAttribute((const void*)gemm_f16_nt<true>,
                         cudaFuncAttributeMaxDynamicSharedMemorySize, SMEM);

    dim3 blk(256);

    // 1. fused prep — one launch
    prep_kernel<<<1024, blk>>>(z, Wq, Wk, Wv, bq, bk, bv, zh, wh, b3);

    // 2. merged QKV projection (plain fp16): [8192,1536] = z @ [Wq|Wk|Wv]^T + b3
    dim3 gp(NQKV / 128, N_ASSET / 128);  // 12 x 64 = 768 CTAs
    gemm_f16_nt<false><<<gp, blk, SMEM>>>(zh, wh, b3,
                                          nullptr, qkv, nullptr, nullptr,
                                          N_ASSET, NQKV, DLAT, DLAT, DLAT, 1.0f);

    const __half* qh = qkv;
    const __half* kh = qkv + DLAT;
    const __half* vh = qkv + 2 * DLAT;

    // 3. transpose v -> [D][N]  (v has ld=1536)
    {
        dim3 tb(32, 8);
        dim3 tg(DLAT / 32, N_ASSET / 32);
        trans_half_kernel<<<tg, tb>>>(vh, vth, N_ASSET, DLAT, NQKV);
    }

    // 4. p = exp(q @ k^T * d^-0.5) -> fp16, plus per-colblock row sums
    dim3 gs(N_ASSET / 128, N_ASSET / 128);  // 64 x 64
    const float scale = 1.0f / sqrtf((float)DLAT);
    gemm_f16_nt<true><<<gs, blk, SMEM>>>(qh, kh, nullptr,
                                         nullptr, p, part, nullptr,
                                         N_ASSET, N_ASSET, DLAT, NQKV, NQKV, scale);

    // 5. zinv[row] = 1 / sum of partials
    zinv_kernel<<<N_ASSET / 256, blk>>>(part, zinv);

    // 6. h = (p @ v) * zinv  (fp32 out)
    dim3 gh(DLAT / 128, N_ASSET / 128);  // 4 x 64
    gemm_f16_nt<false><<<gh, blk, SMEM>>>(p, vth, nullptr,
                                          out, nullptr, nullptr, zinv,
                                          N_ASSET, DLAT, N_ASSET, N_ASSET, N_ASSET, 1.0f);
}